// round 12
// baseline (speedup 1.0000x reference)
#include <cuda_runtime.h>
#include <cuda_fp16.h>

// Problem constants (fixed by the dataset)
#define T_STEPS 8
#define NN      100000
#define EE      1600000
#define FLAT    4096    // 64*64
#define BN      1024    // bottleneck
#define NB_ODE  128     // persistent ODE grid (1 block/SM, co-resident)
#define NB_SCAN 98      // ceil(NN/1024)
#define EPB     64      // edges per block in edge_kernel

// ---------------- device scratch (no allocs allowed) ----------------
__device__ float  g_w[FLAT];
__device__ float  g_ws[FLAT];
__device__ float  g_t[BN];
__device__ float  g_W1t[BN * FLAT];   // transposed: row j (1024 rows) x k (4096)
__device__ float  g_W2t[FLAT * BN];   // transposed: row j (4096 rows) x k (1024)
__device__ int    g_arr[NB_ODE * 32]; // barrier arrival flags (1 line per block)
__device__ int    g_go;               // barrier go flag
__device__ float  g_dis[NN];
__device__ int    g_cnt[NN];        // in-degree (no self)
__device__ int    g_base[NN + 1];   // CSR row offsets (by destination)
__device__ int    g_cur[NN];        // placement cursors
__device__ int    g_src[EE];        // CSR: source node per in-edge
__device__ int    g_bsum[NB_SCAN];
__device__ int    g_boff[NB_SCAN];
__device__ __align__(16) __half2 g_zh[NN * 32];   // dis[n]*(x W_T)  fp16 [N,64]
__device__ __align__(16) __half2 g_hAh[NN * 32];  // h@A+b1 fp16      [N,64]
__device__ __align__(16) __half2 g_hBh[NN * 32];  // h@B    fp16      [N,64]

// ---------------- init: copy w0, zero counters + barrier flags ----------------
__global__ void init_kernel(const float* __restrict__ iw, int n) {
    int i = blockIdx.x * 256 + threadIdx.x;
    if (i == 0) g_go = 0;
    if (i < NB_ODE * 32) g_arr[i] = 0;
    if (i < FLAT) g_w[i] = iw[i];
    if (i < n)    g_cnt[i] = 0;
}

// ---------------- in-degree count ----------------
__global__ void count_kernel(const int* __restrict__ ei, int e) {
    int i = blockIdx.x * 256 + threadIdx.x;
    if (i < e) atomicAdd(&g_cnt[ei[e + i]], 1);
}

// ---------------- dis = rsqrt(deg), deg = cnt + 1 (self loop) ----------------
__global__ void dis_kernel(int n) {
    int i = blockIdx.x * 256 + threadIdx.x;
    if (i < n) g_dis[i] = rsqrtf(1.0f + (float)g_cnt[i]);
}

// ---------------- CSR offset scan (3 small kernels) ----------------
__global__ void scan1_kernel(int n) {            // block sums
    __shared__ int sm_[1024];
    int i = blockIdx.x * 1024 + threadIdx.x;
    sm_[threadIdx.x] = (i < n) ? g_cnt[i] : 0;
    __syncthreads();
#pragma unroll
    for (int o = 512; o; o >>= 1) {
        if (threadIdx.x < o) sm_[threadIdx.x] += sm_[threadIdx.x + o];
        __syncthreads();
    }
    if (threadIdx.x == 0) g_bsum[blockIdx.x] = sm_[0];
}

__global__ void scan2_kernel(int nb) {           // serial scan of block sums
    __shared__ int sb[NB_SCAN];
    if (threadIdx.x < nb) sb[threadIdx.x] = g_bsum[threadIdx.x];
    __syncthreads();
    if (threadIdx.x == 0) {
        int run = 0;
        for (int b = 0; b < nb; ++b) { g_boff[b] = run; run += sb[b]; }
        g_base[NN] = run;            // == EE
    }
}

__global__ void scan3_kernel(int n) {            // in-block exclusive scan + offset
    __shared__ int sm_[1024];
    int i = blockIdx.x * 1024 + threadIdx.x;
    int v = (i < n) ? g_cnt[i] : 0;
    sm_[threadIdx.x] = v;
    __syncthreads();
#pragma unroll
    for (int o = 1; o < 1024; o <<= 1) {         // Hillis-Steele inclusive
        int t = (threadIdx.x >= o) ? sm_[threadIdx.x - o] : 0;
        __syncthreads();
        sm_[threadIdx.x] += t;
        __syncthreads();
    }
    if (i < n) {
        int excl = sm_[threadIdx.x] - v + g_boff[blockIdx.x];
        g_base[i] = excl;
        g_cur[i]  = excl;
    }
}

// ---------------- CSR placement ----------------
__global__ void place_kernel(const int* __restrict__ ei, int e) {
    int i = blockIdx.x * 256 + threadIdx.x;
    if (i < e) {
        int c = ei[e + i];
        int p = atomicAdd(&g_cur[c], 1);
        g_src[p] = ei[i];
    }
}

// ---------------- 32x32 tiled transpose: dst[C][R] = src[R][C]^T ----------------
__global__ void transpose_kernel(const float* __restrict__ src, float* __restrict__ dst,
                                 int R, int C) {
    __shared__ float tile[32][33];
    int bx = blockIdx.x * 32, by = blockIdx.y * 32;
    int x = bx + threadIdx.x;
#pragma unroll
    for (int i = 0; i < 32; i += 8) {
        int y = by + threadIdx.y + i;
        tile[threadIdx.y + i][threadIdx.x] = src[(size_t)y * C + x];
    }
    __syncthreads();
    int x2 = by + threadIdx.x;
#pragma unroll
    for (int i = 0; i < 32; i += 8) {
        int y2 = bx + threadIdx.y + i;
        dst[(size_t)y2 * R + x2] = tile[threadIdx.x][threadIdx.y + i];
    }
}

// ---------------- flag-array grid barrier: NO atomic serialization ----------------
// Each block releases its own flag line; block 0's threads poll them, then one
// thread releases the go flag that all other blocks poll.
__device__ __forceinline__ void gridsync(int gen) {
    __syncthreads();
    if (blockIdx.x == 0) {
        if (threadIdx.x > 0 && threadIdx.x < NB_ODE) {
            int v;
            do {
                asm volatile("ld.acquire.gpu.s32 %0, [%1];"
                             : "=r"(v) : "l"(&g_arr[threadIdx.x * 32]) : "memory");
            } while (v < gen);
        }
        __syncthreads();
        if (threadIdx.x == 0)
            asm volatile("st.release.gpu.s32 [%0], %1;"
                         :: "l"(&g_go), "r"(gen) : "memory");
    } else {
        if (threadIdx.x == 0) {
            asm volatile("st.release.gpu.s32 [%0], %1;"
                         :: "l"(&g_arr[blockIdx.x * 32]), "r"(gen) : "memory");
            int v;
            do {
                asm volatile("ld.acquire.gpu.s32 %0, [%1];"
                             : "=r"(v) : "l"(&g_go) : "memory");
            } while (v < gen);
        }
        __syncthreads();
    }
}

// ---------------- persistent ODE (R7 body, flag barrier) ----------------
#define ODE_SMEM_FLOATS (32768 + 4096 + 1024 + 32)

__global__ __launch_bounds__(1024, 1)
void ode_persist(const float* __restrict__ b1, const float* __restrict__ b2, float h) {
    extern __shared__ float sm[];
    float* sW1 = sm;
    float* sw  = sm + 32768;
    float* st  = sm + 32768 + 4096;
    float* red = sm + 32768 + 4096 + 1024;   // [8 groups][4 warps]

    const int tid  = threadIdx.x;
    const int b    = blockIdx.x;
    const int lane = tid & 31;
    const int wid  = tid >> 5;
    const int grp  = tid >> 7;
    const int tin  = tid & 127;
    const int wgrp = tin >> 5;

    {
        const float4* src = (const float4*)(g_W1t + ((size_t)b * 8) * 4096);
        float4* dst = (float4*)sW1;
#pragma unroll
        for (int i = 0; i < 8; ++i) dst[tid + 1024 * i] = src[tid + 1024 * i];
    }
    float4 w2r[8];
    {
        const float4* src = (const float4*)(g_W2t + ((size_t)(b * 32 + wid)) * 1024);
#pragma unroll
        for (int i = 0; i < 8; ++i) w2r[i] = src[lane + 32 * i];
    }
    const int   j2  = b * 32 + wid;
    const float b2j = b2[j2];
    float wcur = g_w[j2];
    float k1 = 0.f, k2 = 0.f, k3 = 0.f;
    int gen = 0;
    __syncthreads();

    for (int stage = 0; stage < 4 * (T_STEPS - 1); ++stage) {
        const int st4 = stage & 3;
        {
            const float4* win = (const float4*)(st4 == 0 ? g_w : g_ws);
            ((float4*)sw)[tid] = __ldcg(win + tid);
        }
        __syncthreads();

        {
            const float4* wrow = (const float4*)(sW1 + (size_t)grp * 4096);
            const float4* sw4  = (const float4*)sw;
            float s = 0.f;
#pragma unroll
            for (int i = 0; i < 8; ++i) {
                float4 a = wrow[tin + 128 * i];
                float4 v = sw4[tin + 128 * i];
                s += a.x * v.x + a.y * v.y + a.z * v.z + a.w * v.w;
            }
#pragma unroll
            for (int o = 16; o; o >>= 1) s += __shfl_xor_sync(0xffffffffu, s, o);
            if (lane == 0) red[grp * 4 + wgrp] = s;
        }
        __syncthreads();
        if (tid < 8) {
            float tot = red[tid * 4] + red[tid * 4 + 1] + red[tid * 4 + 2] + red[tid * 4 + 3];
            g_t[b * 8 + tid] = tanhf(tot + b1[b * 8 + tid]);
        }
        gridsync(++gen);

        if (tid < 256) ((float4*)st)[tid] = __ldcg(((const float4*)g_t) + tid);
        __syncthreads();
        {
            const float4* st4p = (const float4*)st;
            float s = 0.f;
#pragma unroll
            for (int i = 0; i < 8; ++i) {
                float4 a = w2r[i];
                float4 v = st4p[lane + 32 * i];
                s += a.x * v.x + a.y * v.y + a.z * v.z + a.w * v.w;
            }
#pragma unroll
            for (int o = 16; o; o >>= 1) s += __shfl_xor_sync(0xffffffffu, s, o);
            if (lane == 0) {
                float z = s + b2j;
                if (st4 == 0) {
                    k1 = z;
                    g_ws[j2] = wcur + (h * (1.f / 3.f)) * z;
                } else if (st4 == 1) {
                    k2 = z;
                    g_ws[j2] = wcur + h * (z - k1 * (1.f / 3.f));
                } else if (st4 == 2) {
                    k3 = z;
                    g_ws[j2] = wcur + h * (k1 - k2 + z);
                } else {
                    wcur += h * 0.125f * (k1 + 3.f * (k2 + k3) + z);
                    g_w[j2] = wcur;
                }
            }
        }
        if (stage != 4 * (T_STEPS - 1) - 1) gridsync(++gen);
    }
}

// ---------------- xw: z[n] = dis[n] * (x_last[n] @ W_T), stored fp16 ----------------
__global__ void xw_kernel(const float* __restrict__ xlast, int n) {
    __shared__ float Ws[64 * 64];
    __shared__ float xs[64 * 64];
    int n0 = blockIdx.x * 64;
    for (int i = threadIdx.x; i < 4096; i += 256) Ws[i] = g_w[i];
    for (int i = threadIdx.x; i < 4096; i += 256) {
        int r = i >> 6, c = i & 63, nn = n0 + r;
        xs[i] = (nn < n) ? xlast[(size_t)nn * 64 + c] : 0.f;
    }
    __syncthreads();
    int tx = threadIdx.x & 15, ty = threadIdx.x >> 4;
    float acc[4][4] = {};
#pragma unroll 4
    for (int k = 0; k < 64; ++k) {
        float4 b = *(const float4*)&Ws[k * 64 + tx * 4];
#pragma unroll
        for (int i = 0; i < 4; ++i) {
            float a = xs[(ty * 4 + i) * 64 + k];
            acc[i][0] += a * b.x; acc[i][1] += a * b.y;
            acc[i][2] += a * b.z; acc[i][3] += a * b.w;
        }
    }
#pragma unroll
    for (int i = 0; i < 4; ++i) {
        int nn = n0 + ty * 4 + i;
        if (nn < n) {
            float dn = g_dis[nn];
            __half2 h0 = __floats2half2_rn(dn * acc[i][0], dn * acc[i][1]);
            __half2 h1 = __floats2half2_rn(dn * acc[i][2], dn * acc[i][3]);
            uint2 pk = make_uint2(*(unsigned*)&h0, *(unsigned*)&h1);
            *(uint2*)&g_zh[(size_t)nn * 32 + tx * 2] = pk;
        }
    }
}

// ---------------- fused gather + hA/hB (R7 version) ----------------
__global__ __launch_bounds__(256)
void gatherhab_kernel(const float* __restrict__ mw1, const float* __restrict__ mb1,
                      int n) {
    __shared__ float Ws[64 * 64];
    __shared__ float xs[64 * 64];
    const int tid  = threadIdx.x;
    const int lane = tid & 31;
    const int warp = tid >> 5;
    const int n0   = blockIdx.x * 64;

    // phase 1: each warp gathers 8 nodes -> relu'd rows into the GEMM tile
#pragma unroll 1
    for (int i = 0; i < 8; ++i) {
        int local = warp * 8 + i;
        int nn = n0 + local;
        float2 s = make_float2(0.f, 0.f);
        float dc = 0.f;
        if (nn < n) {
            int k0 = g_base[nn], k1 = g_base[nn + 1];
            s = __half22float2(g_zh[(size_t)nn * 32 + lane]);   // self-loop term
            for (int kb = k0; kb < k1; kb += 32) {
                int m = k1 - kb; if (m > 32) m = 32;
                int rl = (lane < m) ? __ldg(&g_src[kb + lane]) : 0;
#pragma unroll 4
                for (int j = 0; j < m; ++j) {
                    int r = __shfl_sync(0xffffffffu, rl, j);
                    float2 v = __half22float2(g_zh[(size_t)r * 32 + lane]);
                    s.x += v.x; s.y += v.y;
                }
            }
            dc = g_dis[nn];
        }
        *(float2*)&xs[local * 64 + 2 * lane] =
            make_float2(fmaxf(dc * s.x, 0.f), fmaxf(dc * s.y, 0.f));
    }
    __syncthreads();

    // phase 2: hA = relu-tile @ W[0:64] + b1 ; hB = relu-tile @ W[64:128]
    int tx = tid & 15, ty = tid >> 4;
#pragma unroll
    for (int sel = 0; sel < 2; ++sel) {
        if (sel) __syncthreads();
        for (int i = tid; i < 4096; i += 256) Ws[i] = mw1[sel * 4096 + i];
        __syncthreads();
        float acc[4][4] = {};
#pragma unroll 4
        for (int k = 0; k < 64; ++k) {
            float4 b = *(const float4*)&Ws[k * 64 + tx * 4];
#pragma unroll
            for (int i = 0; i < 4; ++i) {
                float a = xs[(ty * 4 + i) * 64 + k];
                acc[i][0] += a * b.x; acc[i][1] += a * b.y;
                acc[i][2] += a * b.z; acc[i][3] += a * b.w;
            }
        }
        float4 bb = make_float4(0.f, 0.f, 0.f, 0.f);
        if (sel == 0) {
            bb.x = mb1[tx * 4 + 0]; bb.y = mb1[tx * 4 + 1];
            bb.z = mb1[tx * 4 + 2]; bb.w = mb1[tx * 4 + 3];
        }
        __half2* out = sel ? g_hBh : g_hAh;
#pragma unroll
        for (int i = 0; i < 4; ++i) {
            int nn = n0 + ty * 4 + i;
            if (nn < n) {
                __half2 h0 = __floats2half2_rn(acc[i][0] + bb.x, acc[i][1] + bb.y);
                __half2 h1 = __floats2half2_rn(acc[i][2] + bb.z, acc[i][3] + bb.w);
                uint2 pk = make_uint2(*(unsigned*)&h0, *(unsigned*)&h1);
                *(uint2*)&out[(size_t)nn * 32 + tx * 2] = pk;
            }
        }
    }
}

// ---------------- edge MLP (R7 version): out[e] = relu(hA[r]+hB[c]+ea@C).w2 + b2 ----------------
__global__ __launch_bounds__(256)
void edge_kernel(const float* __restrict__ ea, const int* __restrict__ ei,
                 const float* __restrict__ mw1, const float* __restrict__ w2,
                 const float* __restrict__ b2, float* __restrict__ out, int e) {
    __shared__ float4 sea[EPB * 4];
    __shared__ int   sr[EPB], sc[EPB];
    __shared__ float sout[EPB];
    const int tid  = threadIdx.x;
    const int lane = tid & 31;
    const int warp = tid >> 5;
    const int e0   = blockIdx.x * EPB;
    const int valid = (e - e0 < EPB) ? (e - e0) : EPB;

    float c0[16], c1[16];
#pragma unroll
    for (int f = 0; f < 16; ++f) {
        float2 cc = *(const float2*)&mw1[(128 + f) * 64 + 2 * lane];
        c0[f] = cc.x; c1[f] = cc.y;
    }
    const float2 w2p = *(const float2*)&w2[2 * lane];
    const float  bb  = __ldg(&b2[0]);

    if (tid < valid * 4) sea[tid] = ((const float4*)(ea + (size_t)e0 * 16))[tid];
    if (tid < valid)                sr[tid]       = __ldg(&ei[e0 + tid]);
    else if (tid >= EPB && tid < EPB + valid) sc[tid - EPB] = __ldg(&ei[e + e0 + (tid - EPB)]);
    __syncthreads();

    if (valid == EPB) {
#pragma unroll 2
        for (int it = 0; it < 8; it += 2) {
            int le0 = warp * 8 + it, le1 = le0 + 1;
            int r0 = sr[le0], cc0 = sc[le0];
            int r1 = sr[le1], cc1 = sc[le1];
            float2 fa0 = __half22float2(g_hAh[(size_t)r0 * 32 + lane]);
            float2 fb0 = __half22float2(g_hBh[(size_t)cc0 * 32 + lane]);
            float2 fa1 = __half22float2(g_hAh[(size_t)r1 * 32 + lane]);
            float2 fb1 = __half22float2(g_hBh[(size_t)cc1 * 32 + lane]);
            float s00 = fa0.x + fb0.x, s01 = fa0.y + fb0.y;
            float s10 = fa1.x + fb1.x, s11 = fa1.y + fb1.y;
#pragma unroll
            for (int q = 0; q < 4; ++q) {
                float4 a0 = sea[le0 * 4 + q];
                float4 a1 = sea[le1 * 4 + q];
                s00 += a0.x * c0[4 * q] + a0.y * c0[4 * q + 1] + a0.z * c0[4 * q + 2] + a0.w * c0[4 * q + 3];
                s01 += a0.x * c1[4 * q] + a0.y * c1[4 * q + 1] + a0.z * c1[4 * q + 2] + a0.w * c1[4 * q + 3];
                s10 += a1.x * c0[4 * q] + a1.y * c0[4 * q + 1] + a1.z * c0[4 * q + 2] + a1.w * c0[4 * q + 3];
                s11 += a1.x * c1[4 * q] + a1.y * c1[4 * q + 1] + a1.z * c1[4 * q + 2] + a1.w * c1[4 * q + 3];
            }
            float p0 = fmaxf(s00, 0.f) * w2p.x + fmaxf(s01, 0.f) * w2p.y;
            float p1 = fmaxf(s10, 0.f) * w2p.x + fmaxf(s11, 0.f) * w2p.y;
#pragma unroll
            for (int o = 16; o; o >>= 1) {
                p0 += __shfl_xor_sync(0xffffffffu, p0, o);
                p1 += __shfl_xor_sync(0xffffffffu, p1, o);
            }
            if (lane == 0) { sout[le0] = p0 + bb; sout[le1] = p1 + bb; }
        }
    } else {
        for (int it = 0; it < 8; ++it) {
            int le = warp * 8 + it;
            if (le < valid) {
                int r = sr[le], c = sc[le];
                float2 fa = __half22float2(g_hAh[(size_t)r * 32 + lane]);
                float2 fb = __half22float2(g_hBh[(size_t)c * 32 + lane]);
                float s0 = fa.x + fb.x;
                float s1 = fa.y + fb.y;
#pragma unroll
                for (int q = 0; q < 4; ++q) {
                    float4 a = sea[le * 4 + q];
                    s0 += a.x * c0[4 * q] + a.y * c0[4 * q + 1] + a.z * c0[4 * q + 2] + a.w * c0[4 * q + 3];
                    s1 += a.x * c1[4 * q] + a.y * c1[4 * q + 1] + a.z * c1[4 * q + 2] + a.w * c1[4 * q + 3];
                }
                float p = fmaxf(s0, 0.f) * w2p.x + fmaxf(s1, 0.f) * w2p.y;
#pragma unroll
                for (int o = 16; o; o >>= 1) p += __shfl_xor_sync(0xffffffffu, p, o);
                if (lane == 0) sout[le] = p + bb;
            }
        }
    }
    __syncthreads();
    if (tid < valid) out[e0 + tid] = sout[tid];
}

// ---------------- launcher ----------------
extern "C" void kernel_launch(void* const* d_in, const int* in_sizes, int n_in,
                              void* d_out, int out_size) {
    const float* x_seq = (const float*)d_in[0];
    const float* ea    = (const float*)d_in[1];
    const float* iw    = (const float*)d_in[2];
    const float* W1    = (const float*)d_in[3];
    const float* b1o   = (const float*)d_in[4];
    const float* W2    = (const float*)d_in[5];
    const float* b2o   = (const float*)d_in[6];
    const float* mw1   = (const float*)d_in[7];
    const float* mb1   = (const float*)d_in[8];
    const float* mw2   = (const float*)d_in[9];
    const float* mb2   = (const float*)d_in[10];
    const int*   ei    = (const int*)d_in[11];
    float* out = (float*)d_out;

    const int n = NN;
    const int e = EE;
    const float* xlast = x_seq + (size_t)(T_STEPS - 1) * n * 64;
    const float h = 1.0f / (float)(T_STEPS - 1);

    cudaFuncSetAttribute(ode_persist, cudaFuncAttributeMaxDynamicSharedMemorySize,
                         ODE_SMEM_FLOATS * 4);

    cudaStream_t sB;
    cudaStreamCreateWithFlags(&sB, cudaStreamNonBlocking);
    cudaEvent_t evFork, evPre, evJoin;
    cudaEventCreateWithFlags(&evFork, cudaEventDisableTiming);
    cudaEventCreateWithFlags(&evPre, cudaEventDisableTiming);
    cudaEventCreateWithFlags(&evJoin, cudaEventDisableTiming);

    // FORK: sB joins the capture graph via an event from the capturing stream.
    cudaEventRecord(evFork, 0);
    cudaStreamWaitEvent(sB, evFork, 0);

    // stream B: init + count + dis (atomic-heavy, pre-ODE), then scans + place
    // (light, overlap the ODE — the R7-measured amount of concurrency).
    init_kernel<<<(n + 255) / 256, 256, 0, sB>>>(iw, n);
    count_kernel<<<(e + 255) / 256, 256, 0, sB>>>(ei, e);
    dis_kernel<<<(n + 255) / 256, 256, 0, sB>>>(n);
    cudaEventRecord(evPre, sB);
    scan1_kernel<<<NB_SCAN, 1024, 0, sB>>>(n);
    scan2_kernel<<<1, 128, 0, sB>>>(NB_SCAN);
    scan3_kernel<<<NB_SCAN, 1024, 0, sB>>>(n);
    place_kernel<<<(e + 255) / 256, 256, 0, sB>>>(ei, e);
    cudaEventRecord(evJoin, sB);

    // main: weight transposes overlap stream B's pre-ODE chain
    {
        float* w1t; cudaGetSymbolAddress((void**)&w1t, g_W1t);
        float* w2t; cudaGetSymbolAddress((void**)&w2t, g_W2t);
        dim3 t1g(BN / 32, FLAT / 32);
        transpose_kernel<<<t1g, dim3(32, 8)>>>(W1, w1t, FLAT, BN);
        dim3 t2g(FLAT / 32, BN / 32);
        transpose_kernel<<<t2g, dim3(32, 8)>>>(W2, w2t, BN, FLAT);
    }
    // ODE waits for init/count/dis; only scans+place run under it.
    cudaStreamWaitEvent(0, evPre, 0);
    ode_persist<<<NB_ODE, 1024, ODE_SMEM_FLOATS * 4>>>(b1o, b2o, h);

    // xw needs only g_w + g_dis — launch right after the ODE
    xw_kernel<<<(n + 63) / 64, 256>>>(xlast, n);

    // JOIN: gather/hab + edge need the CSR from stream B
    cudaStreamWaitEvent(0, evJoin, 0);
    gatherhab_kernel<<<(n + 63) / 64, 256>>>(mw1, mb1, n);
    edge_kernel<<<(e + EPB - 1) / EPB, 256>>>(ea, ei, mw1, mw2, mb2, out, e);

    cudaEventDestroy(evFork);
    cudaEventDestroy(evPre);
    cudaEventDestroy(evJoin);
    cudaStreamDestroy(sB);
}

// round 13
// speedup vs baseline: 1.0842x; 1.0842x over previous
#include <cuda_runtime.h>
#include <cuda_fp16.h>

// Problem constants (fixed by the dataset)
#define T_STEPS 8
#define NN      100000
#define EE      1600000
#define FLAT    4096    // 64*64
#define BN      1024    // bottleneck
#define NB_ODE  128     // persistent ODE grid (1 block/SM, co-resident)
#define NB_SCAN 98      // ceil(NN/1024)
#define EPB     64      // edges per tile in edge_kernel
#define EDGE_BLOCKS 888 // persistent edge grid (6 blocks/SM)

// ---------------- device scratch (no allocs allowed) ----------------
__device__ float  g_w[FLAT];
__device__ float  g_ws[FLAT];
__device__ float  g_t[BN];
__device__ float  g_W1t[BN * FLAT];   // transposed: row j (1024 rows) x k (4096)
__device__ float  g_W2t[FLAT * BN];   // transposed: row j (4096 rows) x k (1024)
__device__ unsigned g_barcnt;
__device__ float  g_dis[NN];
__device__ int    g_cnt[NN];        // in-degree (no self)
__device__ int    g_base[NN + 1];   // CSR row offsets (by destination)
__device__ int    g_cur[NN];        // placement cursors
__device__ int    g_src[EE];        // CSR: source node per in-edge
__device__ int    g_bsum[NB_SCAN];
__device__ int    g_boff[NB_SCAN];
__device__ __align__(16) __half2 g_zh[NN * 32];   // dis[n]*(x W_T)  fp16 [N,64]
__device__ __align__(16) __half2 g_hAh[NN * 32];  // h@A+b1 fp16      [N,64]
__device__ __align__(16) __half2 g_hBh[NN * 32];  // h@B    fp16      [N,64]

// ---------------- init: copy w0, zero counters, reset barrier ----------------
__global__ void init_kernel(const float* __restrict__ iw, int n) {
    int i = blockIdx.x * 256 + threadIdx.x;
    if (i == 0) g_barcnt = 0u;
    if (i < FLAT) g_w[i] = iw[i];
    if (i < n)    g_cnt[i] = 0;
}

// ---------------- in-degree count ----------------
__global__ void count_kernel(const int* __restrict__ ei, int e) {
    int i = blockIdx.x * 256 + threadIdx.x;
    if (i < e) atomicAdd(&g_cnt[ei[e + i]], 1);
}

// ---------------- dis = rsqrt(deg), deg = cnt + 1 (self loop) ----------------
__global__ void dis_kernel(int n) {
    int i = blockIdx.x * 256 + threadIdx.x;
    if (i < n) g_dis[i] = rsqrtf(1.0f + (float)g_cnt[i]);
}

// ---------------- CSR offset scan (3 small kernels) ----------------
__global__ void scan1_kernel(int n) {            // block sums
    __shared__ int sm_[1024];
    int i = blockIdx.x * 1024 + threadIdx.x;
    sm_[threadIdx.x] = (i < n) ? g_cnt[i] : 0;
    __syncthreads();
#pragma unroll
    for (int o = 512; o; o >>= 1) {
        if (threadIdx.x < o) sm_[threadIdx.x] += sm_[threadIdx.x + o];
        __syncthreads();
    }
    if (threadIdx.x == 0) g_bsum[blockIdx.x] = sm_[0];
}

__global__ void scan2_kernel(int nb) {           // serial scan of block sums
    __shared__ int sb[NB_SCAN];
    if (threadIdx.x < nb) sb[threadIdx.x] = g_bsum[threadIdx.x];
    __syncthreads();
    if (threadIdx.x == 0) {
        int run = 0;
        for (int b = 0; b < nb; ++b) { g_boff[b] = run; run += sb[b]; }
        g_base[NN] = run;            // == EE
    }
}

__global__ void scan3_kernel(int n) {            // in-block exclusive scan + offset
    __shared__ int sm_[1024];
    int i = blockIdx.x * 1024 + threadIdx.x;
    int v = (i < n) ? g_cnt[i] : 0;
    sm_[threadIdx.x] = v;
    __syncthreads();
#pragma unroll
    for (int o = 1; o < 1024; o <<= 1) {         // Hillis-Steele inclusive
        int t = (threadIdx.x >= o) ? sm_[threadIdx.x - o] : 0;
        __syncthreads();
        sm_[threadIdx.x] += t;
        __syncthreads();
    }
    if (i < n) {
        int excl = sm_[threadIdx.x] - v + g_boff[blockIdx.x];
        g_base[i] = excl;
        g_cur[i]  = excl;
    }
}

// ---------------- CSR placement ----------------
__global__ void place_kernel(const int* __restrict__ ei, int e) {
    int i = blockIdx.x * 256 + threadIdx.x;
    if (i < e) {
        int c = ei[e + i];
        int p = atomicAdd(&g_cur[c], 1);
        g_src[p] = ei[i];
    }
}

// ---------------- 32x32 tiled transpose: dst[C][R] = src[R][C]^T ----------------
__global__ void transpose_kernel(const float* __restrict__ src, float* __restrict__ dst,
                                 int R, int C) {
    __shared__ float tile[32][33];
    int bx = blockIdx.x * 32, by = blockIdx.y * 32;
    int x = bx + threadIdx.x;
#pragma unroll
    for (int i = 0; i < 32; i += 8) {
        int y = by + threadIdx.y + i;
        tile[threadIdx.y + i][threadIdx.x] = src[(size_t)y * C + x];
    }
    __syncthreads();
    int x2 = by + threadIdx.x;
#pragma unroll
    for (int i = 0; i < 32; i += 8) {
        int y2 = bx + threadIdx.y + i;
        dst[(size_t)y2 * R + x2] = tile[threadIdx.x][threadIdx.y + i];
    }
}

// ---------------- R7 grid barrier: monotonic counter, red.add + acquire poll ----------------
__device__ __forceinline__ void gridsync(unsigned target) {
    __syncthreads();
    if (threadIdx.x == 0) {
        asm volatile("red.add.release.gpu.u32 [%0], %1;"
                     :: "l"(&g_barcnt), "r"(1u) : "memory");
        unsigned v;
        do {
            asm volatile("ld.acquire.gpu.u32 %0, [%1];"
                         : "=r"(v) : "l"(&g_barcnt) : "memory");
        } while (v < target);
    }
    __syncthreads();
}

// ---------------- persistent ODE (R7 byte-for-byte) ----------------
#define ODE_SMEM_FLOATS (32768 + 4096 + 1024 + 32)

__global__ __launch_bounds__(1024, 1)
void ode_persist(const float* __restrict__ b1, const float* __restrict__ b2, float h) {
    extern __shared__ float sm[];
    float* sW1 = sm;
    float* sw  = sm + 32768;
    float* st  = sm + 32768 + 4096;
    float* red = sm + 32768 + 4096 + 1024;   // [8 groups][4 warps]

    const int tid  = threadIdx.x;
    const int b    = blockIdx.x;
    const int lane = tid & 31;
    const int wid  = tid >> 5;
    const int grp  = tid >> 7;
    const int tin  = tid & 127;
    const int wgrp = tin >> 5;

    {
        const float4* src = (const float4*)(g_W1t + ((size_t)b * 8) * 4096);
        float4* dst = (float4*)sW1;
#pragma unroll
        for (int i = 0; i < 8; ++i) dst[tid + 1024 * i] = src[tid + 1024 * i];
    }
    float4 w2r[8];
    {
        const float4* src = (const float4*)(g_W2t + ((size_t)(b * 32 + wid)) * 1024);
#pragma unroll
        for (int i = 0; i < 8; ++i) w2r[i] = src[lane + 32 * i];
    }
    const int   j2  = b * 32 + wid;
    const float b2j = b2[j2];
    float wcur = g_w[j2];
    float k1 = 0.f, k2 = 0.f, k3 = 0.f;
    unsigned tgt = 0;
    __syncthreads();

    for (int stage = 0; stage < 4 * (T_STEPS - 1); ++stage) {
        const int st4 = stage & 3;
        {
            const float4* win = (const float4*)(st4 == 0 ? g_w : g_ws);
            ((float4*)sw)[tid] = __ldcg(win + tid);
        }
        __syncthreads();

        {
            const float4* wrow = (const float4*)(sW1 + (size_t)grp * 4096);
            const float4* sw4  = (const float4*)sw;
            float s = 0.f;
#pragma unroll
            for (int i = 0; i < 8; ++i) {
                float4 a = wrow[tin + 128 * i];
                float4 v = sw4[tin + 128 * i];
                s += a.x * v.x + a.y * v.y + a.z * v.z + a.w * v.w;
            }
#pragma unroll
            for (int o = 16; o; o >>= 1) s += __shfl_xor_sync(0xffffffffu, s, o);
            if (lane == 0) red[grp * 4 + wgrp] = s;
        }
        __syncthreads();
        if (tid < 8) {
            float tot = red[tid * 4] + red[tid * 4 + 1] + red[tid * 4 + 2] + red[tid * 4 + 3];
            g_t[b * 8 + tid] = tanhf(tot + b1[b * 8 + tid]);
        }
        tgt += NB_ODE;
        gridsync(tgt);

        if (tid < 256) ((float4*)st)[tid] = __ldcg(((const float4*)g_t) + tid);
        __syncthreads();
        {
            const float4* st4p = (const float4*)st;
            float s = 0.f;
#pragma unroll
            for (int i = 0; i < 8; ++i) {
                float4 a = w2r[i];
                float4 v = st4p[lane + 32 * i];
                s += a.x * v.x + a.y * v.y + a.z * v.z + a.w * v.w;
            }
#pragma unroll
            for (int o = 16; o; o >>= 1) s += __shfl_xor_sync(0xffffffffu, s, o);
            if (lane == 0) {
                float z = s + b2j;
                if (st4 == 0) {
                    k1 = z;
                    g_ws[j2] = wcur + (h * (1.f / 3.f)) * z;
                } else if (st4 == 1) {
                    k2 = z;
                    g_ws[j2] = wcur + h * (z - k1 * (1.f / 3.f));
                } else if (st4 == 2) {
                    k3 = z;
                    g_ws[j2] = wcur + h * (k1 - k2 + z);
                } else {
                    wcur += h * 0.125f * (k1 + 3.f * (k2 + k3) + z);
                    g_w[j2] = wcur;
                }
            }
        }
        if (stage != 4 * (T_STEPS - 1) - 1) {
            tgt += NB_ODE;
            gridsync(tgt);
        }
    }
}

// ---------------- xw: z[n] = dis[n] * (x_last[n] @ W_T), stored fp16 (R7) ----------------
__global__ void xw_kernel(const float* __restrict__ xlast, int n) {
    __shared__ float Ws[64 * 64];
    __shared__ float xs[64 * 64];
    int n0 = blockIdx.x * 64;
    for (int i = threadIdx.x; i < 4096; i += 256) Ws[i] = g_w[i];
    for (int i = threadIdx.x; i < 4096; i += 256) {
        int r = i >> 6, c = i & 63, nn = n0 + r;
        xs[i] = (nn < n) ? xlast[(size_t)nn * 64 + c] : 0.f;
    }
    __syncthreads();
    int tx = threadIdx.x & 15, ty = threadIdx.x >> 4;
    float acc[4][4] = {};
#pragma unroll 4
    for (int k = 0; k < 64; ++k) {
        float4 b = *(const float4*)&Ws[k * 64 + tx * 4];
#pragma unroll
        for (int i = 0; i < 4; ++i) {
            float a = xs[(ty * 4 + i) * 64 + k];
            acc[i][0] += a * b.x; acc[i][1] += a * b.y;
            acc[i][2] += a * b.z; acc[i][3] += a * b.w;
        }
    }
#pragma unroll
    for (int i = 0; i < 4; ++i) {
        int nn = n0 + ty * 4 + i;
        if (nn < n) {
            float dn = g_dis[nn];
            __half2 h0 = __floats2half2_rn(dn * acc[i][0], dn * acc[i][1]);
            __half2 h1 = __floats2half2_rn(dn * acc[i][2], dn * acc[i][3]);
            uint2 pk = make_uint2(*(unsigned*)&h0, *(unsigned*)&h1);
            *(uint2*)&g_zh[(size_t)nn * 32 + tx * 2] = pk;
        }
    }
}

// ---------------- fused gather + hA/hB (R7 byte-for-byte) ----------------
__global__ __launch_bounds__(256)
void gatherhab_kernel(const float* __restrict__ mw1, const float* __restrict__ mb1,
                      int n) {
    __shared__ float Ws[64 * 64];
    __shared__ float xs[64 * 64];
    const int tid  = threadIdx.x;
    const int lane = tid & 31;
    const int warp = tid >> 5;
    const int n0   = blockIdx.x * 64;

#pragma unroll 1
    for (int i = 0; i < 8; ++i) {
        int local = warp * 8 + i;
        int nn = n0 + local;
        float2 s = make_float2(0.f, 0.f);
        float dc = 0.f;
        if (nn < n) {
            int k0 = g_base[nn], k1 = g_base[nn + 1];
            s = __half22float2(g_zh[(size_t)nn * 32 + lane]);   // self-loop term
            for (int kb = k0; kb < k1; kb += 32) {
                int m = k1 - kb; if (m > 32) m = 32;
                int rl = (lane < m) ? __ldg(&g_src[kb + lane]) : 0;
#pragma unroll 4
                for (int j = 0; j < m; ++j) {
                    int r = __shfl_sync(0xffffffffu, rl, j);
                    float2 v = __half22float2(g_zh[(size_t)r * 32 + lane]);
                    s.x += v.x; s.y += v.y;
                }
            }
            dc = g_dis[nn];
        }
        *(float2*)&xs[local * 64 + 2 * lane] =
            make_float2(fmaxf(dc * s.x, 0.f), fmaxf(dc * s.y, 0.f));
    }
    __syncthreads();

    int tx = tid & 15, ty = tid >> 4;
#pragma unroll
    for (int sel = 0; sel < 2; ++sel) {
        if (sel) __syncthreads();
        for (int i = tid; i < 4096; i += 256) Ws[i] = mw1[sel * 4096 + i];
        __syncthreads();
        float acc[4][4] = {};
#pragma unroll 4
        for (int k = 0; k < 64; ++k) {
            float4 b = *(const float4*)&Ws[k * 64 + tx * 4];
#pragma unroll
            for (int i = 0; i < 4; ++i) {
                float a = xs[(ty * 4 + i) * 64 + k];
                acc[i][0] += a * b.x; acc[i][1] += a * b.y;
                acc[i][2] += a * b.z; acc[i][3] += a * b.w;
            }
        }
        float4 bb = make_float4(0.f, 0.f, 0.f, 0.f);
        if (sel == 0) {
            bb.x = mb1[tx * 4 + 0]; bb.y = mb1[tx * 4 + 1];
            bb.z = mb1[tx * 4 + 2]; bb.w = mb1[tx * 4 + 3];
        }
        __half2* out = sel ? g_hBh : g_hAh;
#pragma unroll
        for (int i = 0; i < 4; ++i) {
            int nn = n0 + ty * 4 + i;
            if (nn < n) {
                __half2 h0 = __floats2half2_rn(acc[i][0] + bb.x, acc[i][1] + bb.y);
                __half2 h1 = __floats2half2_rn(acc[i][2] + bb.z, acc[i][3] + bb.w);
                uint2 pk = make_uint2(*(unsigned*)&h0, *(unsigned*)&h1);
                *(uint2*)&out[(size_t)nn * 32 + tx * 2] = pk;
            }
        }
    }
}

// ---------------- persistent edge MLP: grid-stride over 64-edge tiles ----------------
// C columns / w2 / bias loaded ONCE per block (888 blocks instead of 25000).
__global__ __launch_bounds__(256)
void edge_kernel(const float* __restrict__ ea, const int* __restrict__ ei,
                 const float* __restrict__ mw1, const float* __restrict__ w2,
                 const float* __restrict__ b2, float* __restrict__ out, int e) {
    __shared__ float4 sea[EPB * 4];
    __shared__ int   sr[EPB], sc[EPB];
    __shared__ float sout[EPB];
    const int tid  = threadIdx.x;
    const int lane = tid & 31;
    const int warp = tid >> 5;

    // edge-invariant operands -> registers (once per persistent block)
    float c0[16], c1[16];
#pragma unroll
    for (int f = 0; f < 16; ++f) {
        float2 cc = *(const float2*)&mw1[(128 + f) * 64 + 2 * lane];
        c0[f] = cc.x; c1[f] = cc.y;
    }
    const float2 w2p = *(const float2*)&w2[2 * lane];
    const float  bb  = __ldg(&b2[0]);

    const int ntiles = (e + EPB - 1) / EPB;
    for (int t = blockIdx.x; t < ntiles; t += gridDim.x) {
        const int e0 = t * EPB;
        const int valid = (e - e0 < EPB) ? (e - e0) : EPB;

        if (tid < valid * 4) sea[tid] = ((const float4*)(ea + (size_t)e0 * 16))[tid];
        if (tid < valid)                sr[tid]       = __ldg(&ei[e0 + tid]);
        else if (tid >= EPB && tid < EPB + valid) sc[tid - EPB] = __ldg(&ei[e + e0 + (tid - EPB)]);
        __syncthreads();

        if (valid == EPB) {
#pragma unroll 2
            for (int it = 0; it < 8; it += 2) {
                int le0 = warp * 8 + it, le1 = le0 + 1;
                int r0 = sr[le0], cc0 = sc[le0];
                int r1 = sr[le1], cc1 = sc[le1];
                float2 fa0 = __half22float2(g_hAh[(size_t)r0 * 32 + lane]);
                float2 fb0 = __half22float2(g_hBh[(size_t)cc0 * 32 + lane]);
                float2 fa1 = __half22float2(g_hAh[(size_t)r1 * 32 + lane]);
                float2 fb1 = __half22float2(g_hBh[(size_t)cc1 * 32 + lane]);
                float s00 = fa0.x + fb0.x, s01 = fa0.y + fb0.y;
                float s10 = fa1.x + fb1.x, s11 = fa1.y + fb1.y;
#pragma unroll
                for (int q = 0; q < 4; ++q) {
                    float4 a0 = sea[le0 * 4 + q];
                    float4 a1 = sea[le1 * 4 + q];
                    s00 += a0.x * c0[4 * q] + a0.y * c0[4 * q + 1] + a0.z * c0[4 * q + 2] + a0.w * c0[4 * q + 3];
                    s01 += a0.x * c1[4 * q] + a0.y * c1[4 * q + 1] + a0.z * c1[4 * q + 2] + a0.w * c1[4 * q + 3];
                    s10 += a1.x * c0[4 * q] + a1.y * c0[4 * q + 1] + a1.z * c0[4 * q + 2] + a1.w * c0[4 * q + 3];
                    s11 += a1.x * c1[4 * q] + a1.y * c1[4 * q + 1] + a1.z * c1[4 * q + 2] + a1.w * c1[4 * q + 3];
                }
                float p0 = fmaxf(s00, 0.f) * w2p.x + fmaxf(s01, 0.f) * w2p.y;
                float p1 = fmaxf(s10, 0.f) * w2p.x + fmaxf(s11, 0.f) * w2p.y;
#pragma unroll
                for (int o = 16; o; o >>= 1) {
                    p0 += __shfl_xor_sync(0xffffffffu, p0, o);
                    p1 += __shfl_xor_sync(0xffffffffu, p1, o);
                }
                if (lane == 0) { sout[le0] = p0 + bb; sout[le1] = p1 + bb; }
            }
        } else {
            for (int it = 0; it < 8; ++it) {
                int le = warp * 8 + it;
                if (le < valid) {
                    int r = sr[le], c = sc[le];
                    float2 fa = __half22float2(g_hAh[(size_t)r * 32 + lane]);
                    float2 fb = __half22float2(g_hBh[(size_t)c * 32 + lane]);
                    float s0 = fa.x + fb.x;
                    float s1 = fa.y + fb.y;
#pragma unroll
                    for (int q = 0; q < 4; ++q) {
                        float4 a = sea[le * 4 + q];
                        s0 += a.x * c0[4 * q] + a.y * c0[4 * q + 1] + a.z * c0[4 * q + 2] + a.w * c0[4 * q + 3];
                        s1 += a.x * c1[4 * q] + a.y * c1[4 * q + 1] + a.z * c1[4 * q + 2] + a.w * c1[4 * q + 3];
                    }
                    float p = fmaxf(s0, 0.f) * w2p.x + fmaxf(s1, 0.f) * w2p.y;
#pragma unroll
                    for (int o = 16; o; o >>= 1) p += __shfl_xor_sync(0xffffffffu, p, o);
                    if (lane == 0) sout[le] = p + bb;
                }
            }
        }
        __syncthreads();
        if (tid < valid) out[e0 + tid] = sout[tid];
        __syncthreads();   // sea/sout reuse hazard before next tile
    }
}

// ---------------- launcher (R7 schedule byte-for-byte) ----------------
extern "C" void kernel_launch(void* const* d_in, const int* in_sizes, int n_in,
                              void* d_out, int out_size) {
    const float* x_seq = (const float*)d_in[0];
    const float* ea    = (const float*)d_in[1];
    const float* iw    = (const float*)d_in[2];
    const float* W1    = (const float*)d_in[3];
    const float* b1o   = (const float*)d_in[4];
    const float* W2    = (const float*)d_in[5];
    const float* b2o   = (const float*)d_in[6];
    const float* mw1   = (const float*)d_in[7];
    const float* mb1   = (const float*)d_in[8];
    const float* mw2   = (const float*)d_in[9];
    const float* mb2   = (const float*)d_in[10];
    const int*   ei    = (const int*)d_in[11];
    float* out = (float*)d_out;

    const int n = NN;
    const int e = EE;
    const float* xlast = x_seq + (size_t)(T_STEPS - 1) * n * 64;
    const float h = 1.0f / (float)(T_STEPS - 1);

    cudaFuncSetAttribute(ode_persist, cudaFuncAttributeMaxDynamicSharedMemorySize,
                         ODE_SMEM_FLOATS * 4);

    cudaStream_t sB;
    cudaStreamCreateWithFlags(&sB, cudaStreamNonBlocking);
    cudaEvent_t evFork, evInit, evJoin;
    cudaEventCreateWithFlags(&evFork, cudaEventDisableTiming);
    cudaEventCreateWithFlags(&evInit, cudaEventDisableTiming);
    cudaEventCreateWithFlags(&evJoin, cudaEventDisableTiming);

    // main: weight transposes (dependency-free) start immediately
    {
        float* w1t; cudaGetSymbolAddress((void**)&w1t, g_W1t);
        float* w2t; cudaGetSymbolAddress((void**)&w2t, g_W2t);
        dim3 t1g(BN / 32, FLAT / 32);
        transpose_kernel<<<t1g, dim3(32, 8)>>>(W1, w1t, FLAT, BN);
        dim3 t2g(FLAT / 32, BN / 32);
        transpose_kernel<<<t2g, dim3(32, 8)>>>(W2, w2t, BN, FLAT);
    }
    // FORK: sB joins the capture graph via an event from the capturing stream.
    cudaEventRecord(evFork, 0);
    cudaStreamWaitEvent(sB, evFork, 0);

    // stream B: init + whole CSR/normalization chain (R7 schedule)
    init_kernel<<<(n + 255) / 256, 256, 0, sB>>>(iw, n);
    cudaEventRecord(evInit, sB);
    count_kernel<<<(e + 255) / 256, 256, 0, sB>>>(ei, e);
    dis_kernel<<<(n + 255) / 256, 256, 0, sB>>>(n);
    scan1_kernel<<<NB_SCAN, 1024, 0, sB>>>(n);
    scan2_kernel<<<1, 128, 0, sB>>>(NB_SCAN);
    scan3_kernel<<<NB_SCAN, 1024, 0, sB>>>(n);
    place_kernel<<<(e + 255) / 256, 256, 0, sB>>>(ei, e);
    cudaEventRecord(evJoin, sB);

    // main: ODE starts as soon as init is done; CSR chain runs under it.
    cudaStreamWaitEvent(0, evInit, 0);
    ode_persist<<<NB_ODE, 1024, ODE_SMEM_FLOATS * 4>>>(b1o, b2o, h);

    // JOIN: GCN needs g_dis + CSR from sB
    cudaStreamWaitEvent(0, evJoin, 0);
    xw_kernel<<<(n + 63) / 64, 256>>>(xlast, n);
    gatherhab_kernel<<<(n + 63) / 64, 256>>>(mw1, mb1, n);
    edge_kernel<<<EDGE_BLOCKS, 256>>>(ea, ei, mw1, mw2, mb2, out, e);

    cudaEventDestroy(evFork);
    cudaEventDestroy(evInit);
    cudaEventDestroy(evJoin);
    cudaStreamDestroy(sB);
}

// round 14
// speedup vs baseline: 1.2223x; 1.1274x over previous
#include <cuda_runtime.h>
#include <cuda_fp16.h>

// Problem constants (fixed by the dataset)
#define T_STEPS 8
#define NN      100000
#define EE      1600000
#define FLAT    4096    // 64*64
#define BN      1024    // bottleneck
#define NB_ODE  128     // persistent ODE grid (1 block/SM, co-resident)
#define NB_SCAN 98      // ceil(NN/1024)
#define EPB     64      // edges per block in edge_kernel

// ---------------- device scratch (no allocs allowed) ----------------
__device__ float  g_w[FLAT];
__device__ float  g_ws[FLAT];
__device__ float  g_t[BN];
__device__ float  g_W1t[BN * FLAT];   // transposed: row j (1024 rows) x k (4096)
__device__ float  g_W2t[FLAT * BN];   // transposed: row j (4096 rows) x k (1024)
__device__ unsigned g_barcnt;
__device__ float  g_dis[NN];
__device__ int    g_cnt[NN];        // in-degree (no self)
__device__ int    g_base[NN + 1];   // CSR row offsets (by destination)
__device__ int    g_cur[NN];        // placement cursors
__device__ int    g_src[EE];        // CSR: source node per in-edge
__device__ int    g_bsum[NB_SCAN];
__device__ int    g_boff[NB_SCAN];
__device__ __align__(16) __half2 g_zh[NN * 32];    // zx = dis[n]*x[n]  fp16 [N,64]
__device__ __align__(16) __half2 g_xaggh[NN * 32]; // aggregated x      fp16 [N,64]
__device__ __align__(16) __half2 g_hAh[NN * 32];   // h@A+b1 fp16       [N,64]
__device__ __align__(16) __half2 g_hBh[NN * 32];   // h@B    fp16       [N,64]

// ---------------- init: copy w0, zero counters, reset barrier ----------------
__global__ void init_kernel(const float* __restrict__ iw, int n) {
    int i = blockIdx.x * 256 + threadIdx.x;
    if (i == 0) g_barcnt = 0u;
    if (i < FLAT) g_w[i] = iw[i];
    if (i < n)    g_cnt[i] = 0;
}

// ---------------- in-degree count ----------------
__global__ void count_kernel(const int* __restrict__ ei, int e) {
    int i = blockIdx.x * 256 + threadIdx.x;
    if (i < e) atomicAdd(&g_cnt[ei[e + i]], 1);
}

// ---------------- dis = rsqrt(deg), deg = cnt + 1 (self loop) ----------------
__global__ void dis_kernel(int n) {
    int i = blockIdx.x * 256 + threadIdx.x;
    if (i < n) g_dis[i] = rsqrtf(1.0f + (float)g_cnt[i]);
}

// ---------------- zx[n] = dis[n] * x_last[n], stored fp16 ----------------
__global__ void zxh_kernel(const float* __restrict__ xlast, int n) {
    int idx = blockIdx.x * 256 + threadIdx.x;     // half2 index
    if (idx < n * 32) {
        int nn = idx >> 5;
        float d = g_dis[nn];
        float2 v = ((const float2*)xlast)[idx];
        g_zh[idx] = __floats2half2_rn(d * v.x, d * v.y);
    }
}

// ---------------- CSR offset scan (3 small kernels) ----------------
__global__ void scan1_kernel(int n) {            // block sums
    __shared__ int sm_[1024];
    int i = blockIdx.x * 1024 + threadIdx.x;
    sm_[threadIdx.x] = (i < n) ? g_cnt[i] : 0;
    __syncthreads();
#pragma unroll
    for (int o = 512; o; o >>= 1) {
        if (threadIdx.x < o) sm_[threadIdx.x] += sm_[threadIdx.x + o];
        __syncthreads();
    }
    if (threadIdx.x == 0) g_bsum[blockIdx.x] = sm_[0];
}

__global__ void scan2_kernel(int nb) {           // serial scan of block sums
    __shared__ int sb[NB_SCAN];
    if (threadIdx.x < nb) sb[threadIdx.x] = g_bsum[threadIdx.x];
    __syncthreads();
    if (threadIdx.x == 0) {
        int run = 0;
        for (int b = 0; b < nb; ++b) { g_boff[b] = run; run += sb[b]; }
        g_base[NN] = run;            // == EE
    }
}

__global__ void scan3_kernel(int n) {            // in-block exclusive scan + offset
    __shared__ int sm_[1024];
    int i = blockIdx.x * 1024 + threadIdx.x;
    int v = (i < n) ? g_cnt[i] : 0;
    sm_[threadIdx.x] = v;
    __syncthreads();
#pragma unroll
    for (int o = 1; o < 1024; o <<= 1) {         // Hillis-Steele inclusive
        int t = (threadIdx.x >= o) ? sm_[threadIdx.x - o] : 0;
        __syncthreads();
        sm_[threadIdx.x] += t;
        __syncthreads();
    }
    if (i < n) {
        int excl = sm_[threadIdx.x] - v + g_boff[blockIdx.x];
        g_base[i] = excl;
        g_cur[i]  = excl;
    }
}

// ---------------- CSR placement ----------------
__global__ void place_kernel(const int* __restrict__ ei, int e) {
    int i = blockIdx.x * 256 + threadIdx.x;
    if (i < e) {
        int c = ei[e + i];
        int p = atomicAdd(&g_cur[c], 1);
        g_src[p] = ei[i];
    }
}

// ---------------- X_agg[c] = dis[c]*(zx[c] + sum_in zx[src]), fp16; W-independent ----------------
__global__ void xagg_kernel(int n) {
    int gw   = (blockIdx.x * 256 + threadIdx.x) >> 5;
    int lane = threadIdx.x & 31;
    if (gw >= n) return;
    int k0 = g_base[gw], k1 = g_base[gw + 1];
    float2 s = __half22float2(g_zh[(size_t)gw * 32 + lane]);   // self-loop term
    for (int kb = k0; kb < k1; kb += 32) {
        int m = k1 - kb; if (m > 32) m = 32;
        int rl = (lane < m) ? __ldg(&g_src[kb + lane]) : 0;
#pragma unroll 4
        for (int j = 0; j < m; ++j) {
            int r = __shfl_sync(0xffffffffu, rl, j);
            float2 v = __half22float2(g_zh[(size_t)r * 32 + lane]);
            s.x += v.x; s.y += v.y;
        }
    }
    float dc = g_dis[gw];
    g_xaggh[(size_t)gw * 32 + lane] = __floats2half2_rn(dc * s.x, dc * s.y);
}

// ---------------- 32x32 tiled transpose: dst[C][R] = src[R][C]^T ----------------
__global__ void transpose_kernel(const float* __restrict__ src, float* __restrict__ dst,
                                 int R, int C) {
    __shared__ float tile[32][33];
    int bx = blockIdx.x * 32, by = blockIdx.y * 32;
    int x = bx + threadIdx.x;
#pragma unroll
    for (int i = 0; i < 32; i += 8) {
        int y = by + threadIdx.y + i;
        tile[threadIdx.y + i][threadIdx.x] = src[(size_t)y * C + x];
    }
    __syncthreads();
    int x2 = by + threadIdx.x;
#pragma unroll
    for (int i = 0; i < 32; i += 8) {
        int y2 = bx + threadIdx.y + i;
        dst[(size_t)y2 * R + x2] = tile[threadIdx.x][threadIdx.y + i];
    }
}

// ---------------- R7 grid barrier: monotonic counter, red.add + acquire poll ----------------
__device__ __forceinline__ void gridsync(unsigned target) {
    __syncthreads();
    if (threadIdx.x == 0) {
        asm volatile("red.add.release.gpu.u32 [%0], %1;"
                     :: "l"(&g_barcnt), "r"(1u) : "memory");
        unsigned v;
        do {
            asm volatile("ld.acquire.gpu.u32 %0, [%1];"
                         : "=r"(v) : "l"(&g_barcnt) : "memory");
        } while (v < target);
    }
    __syncthreads();
}

// ---------------- persistent ODE (R7 byte-for-byte) ----------------
#define ODE_SMEM_FLOATS (32768 + 4096 + 1024 + 32)

__global__ __launch_bounds__(1024, 1)
void ode_persist(const float* __restrict__ b1, const float* __restrict__ b2, float h) {
    extern __shared__ float sm[];
    float* sW1 = sm;
    float* sw  = sm + 32768;
    float* st  = sm + 32768 + 4096;
    float* red = sm + 32768 + 4096 + 1024;   // [8 groups][4 warps]

    const int tid  = threadIdx.x;
    const int b    = blockIdx.x;
    const int lane = tid & 31;
    const int wid  = tid >> 5;
    const int grp  = tid >> 7;
    const int tin  = tid & 127;
    const int wgrp = tin >> 5;

    {
        const float4* src = (const float4*)(g_W1t + ((size_t)b * 8) * 4096);
        float4* dst = (float4*)sW1;
#pragma unroll
        for (int i = 0; i < 8; ++i) dst[tid + 1024 * i] = src[tid + 1024 * i];
    }
    float4 w2r[8];
    {
        const float4* src = (const float4*)(g_W2t + ((size_t)(b * 32 + wid)) * 1024);
#pragma unroll
        for (int i = 0; i < 8; ++i) w2r[i] = src[lane + 32 * i];
    }
    const int   j2  = b * 32 + wid;
    const float b2j = b2[j2];
    float wcur = g_w[j2];
    float k1 = 0.f, k2 = 0.f, k3 = 0.f;
    unsigned tgt = 0;
    __syncthreads();

    for (int stage = 0; stage < 4 * (T_STEPS - 1); ++stage) {
        const int st4 = stage & 3;
        {
            const float4* win = (const float4*)(st4 == 0 ? g_w : g_ws);
            ((float4*)sw)[tid] = __ldcg(win + tid);
        }
        __syncthreads();

        {
            const float4* wrow = (const float4*)(sW1 + (size_t)grp * 4096);
            const float4* sw4  = (const float4*)sw;
            float s = 0.f;
#pragma unroll
            for (int i = 0; i < 8; ++i) {
                float4 a = wrow[tin + 128 * i];
                float4 v = sw4[tin + 128 * i];
                s += a.x * v.x + a.y * v.y + a.z * v.z + a.w * v.w;
            }
#pragma unroll
            for (int o = 16; o; o >>= 1) s += __shfl_xor_sync(0xffffffffu, s, o);
            if (lane == 0) red[grp * 4 + wgrp] = s;
        }
        __syncthreads();
        if (tid < 8) {
            float tot = red[tid * 4] + red[tid * 4 + 1] + red[tid * 4 + 2] + red[tid * 4 + 3];
            g_t[b * 8 + tid] = tanhf(tot + b1[b * 8 + tid]);
        }
        tgt += NB_ODE;
        gridsync(tgt);

        if (tid < 256) ((float4*)st)[tid] = __ldcg(((const float4*)g_t) + tid);
        __syncthreads();
        {
            const float4* st4p = (const float4*)st;
            float s = 0.f;
#pragma unroll
            for (int i = 0; i < 8; ++i) {
                float4 a = w2r[i];
                float4 v = st4p[lane + 32 * i];
                s += a.x * v.x + a.y * v.y + a.z * v.z + a.w * v.w;
            }
#pragma unroll
            for (int o = 16; o; o >>= 1) s += __shfl_xor_sync(0xffffffffu, s, o);
            if (lane == 0) {
                float z = s + b2j;
                if (st4 == 0) {
                    k1 = z;
                    g_ws[j2] = wcur + (h * (1.f / 3.f)) * z;
                } else if (st4 == 1) {
                    k2 = z;
                    g_ws[j2] = wcur + h * (z - k1 * (1.f / 3.f));
                } else if (st4 == 2) {
                    k3 = z;
                    g_ws[j2] = wcur + h * (k1 - k2 + z);
                } else {
                    wcur += h * 0.125f * (k1 + 3.f * (k2 + k3) + z);
                    g_w[j2] = wcur;
                }
            }
        }
        if (stage != 4 * (T_STEPS - 1) - 1) {
            tgt += NB_ODE;
            gridsync(tgt);
        }
    }
}

// ---------------- fused: u = Xagg @ W; h = relu(u); hA = h@A+b1; hB = h@B ----------------
__global__ __launch_bounds__(256)
void wxhab_kernel(const float* __restrict__ mw1, const float* __restrict__ mb1,
                  int n) {
    __shared__ float Ws[64 * 64];
    __shared__ float xs[64 * 64];
    const int tid = threadIdx.x;
    const int n0  = blockIdx.x * 64;

    // stage X_agg tile (fp16 -> fp32)
    for (int i = tid; i < 2048; i += 256) {
        int r = i >> 5, c2 = i & 31, nn = n0 + r;
        float2 v = (nn < n) ? __half22float2(g_xaggh[(size_t)nn * 32 + c2])
                            : make_float2(0.f, 0.f);
        *(float2*)&xs[r * 64 + 2 * c2] = v;
    }
    for (int i = tid; i < 4096; i += 256) Ws[i] = g_w[i];
    __syncthreads();

    int tx = tid & 15, ty = tid >> 4;

    // GEMM 1: u = Xagg @ W
    float acc[4][4] = {};
#pragma unroll 4
    for (int k = 0; k < 64; ++k) {
        float4 b = *(const float4*)&Ws[k * 64 + tx * 4];
#pragma unroll
        for (int i = 0; i < 4; ++i) {
            float a = xs[(ty * 4 + i) * 64 + k];
            acc[i][0] += a * b.x; acc[i][1] += a * b.y;
            acc[i][2] += a * b.z; acc[i][3] += a * b.w;
        }
    }
    __syncthreads();    // all reads of xs done

    // write relu'd u back into xs
#pragma unroll
    for (int i = 0; i < 4; ++i) {
        int row = ty * 4 + i;
        xs[row * 64 + tx * 4 + 0] = fmaxf(acc[i][0], 0.f);
        xs[row * 64 + tx * 4 + 1] = fmaxf(acc[i][1], 0.f);
        xs[row * 64 + tx * 4 + 2] = fmaxf(acc[i][2], 0.f);
        xs[row * 64 + tx * 4 + 3] = fmaxf(acc[i][3], 0.f);
    }

    // GEMM 2/3: hA = h@A + b1 ; hB = h@B
#pragma unroll
    for (int sel = 0; sel < 2; ++sel) {
        __syncthreads();
        for (int i = tid; i < 4096; i += 256) Ws[i] = mw1[sel * 4096 + i];
        __syncthreads();
        float acc2[4][4] = {};
#pragma unroll 4
        for (int k = 0; k < 64; ++k) {
            float4 b = *(const float4*)&Ws[k * 64 + tx * 4];
#pragma unroll
            for (int i = 0; i < 4; ++i) {
                float a = xs[(ty * 4 + i) * 64 + k];
                acc2[i][0] += a * b.x; acc2[i][1] += a * b.y;
                acc2[i][2] += a * b.z; acc2[i][3] += a * b.w;
            }
        }
        float4 bb = make_float4(0.f, 0.f, 0.f, 0.f);
        if (sel == 0) {
            bb.x = mb1[tx * 4 + 0]; bb.y = mb1[tx * 4 + 1];
            bb.z = mb1[tx * 4 + 2]; bb.w = mb1[tx * 4 + 3];
        }
        __half2* out = sel ? g_hBh : g_hAh;
#pragma unroll
        for (int i = 0; i < 4; ++i) {
            int nn = n0 + ty * 4 + i;
            if (nn < n) {
                __half2 h0 = __floats2half2_rn(acc2[i][0] + bb.x, acc2[i][1] + bb.y);
                __half2 h1 = __floats2half2_rn(acc2[i][2] + bb.z, acc2[i][3] + bb.w);
                uint2 pk = make_uint2(*(unsigned*)&h0, *(unsigned*)&h1);
                *(uint2*)&out[(size_t)nn * 32 + tx * 2] = pk;
            }
        }
    }
}

// ---------------- edge MLP (R7 version, 25000 blocks) ----------------
__global__ __launch_bounds__(256)
void edge_kernel(const float* __restrict__ ea, const int* __restrict__ ei,
                 const float* __restrict__ mw1, const float* __restrict__ w2,
                 const float* __restrict__ b2, float* __restrict__ out, int e) {
    __shared__ float4 sea[EPB * 4];
    __shared__ int   sr[EPB], sc[EPB];
    __shared__ float sout[EPB];
    const int tid  = threadIdx.x;
    const int lane = tid & 31;
    const int warp = tid >> 5;
    const int e0   = blockIdx.x * EPB;
    const int valid = (e - e0 < EPB) ? (e - e0) : EPB;

    float c0[16], c1[16];
#pragma unroll
    for (int f = 0; f < 16; ++f) {
        float2 cc = *(const float2*)&mw1[(128 + f) * 64 + 2 * lane];
        c0[f] = cc.x; c1[f] = cc.y;
    }
    const float2 w2p = *(const float2*)&w2[2 * lane];
    const float  bb  = __ldg(&b2[0]);

    if (tid < valid * 4) sea[tid] = ((const float4*)(ea + (size_t)e0 * 16))[tid];
    if (tid < valid)                sr[tid]       = __ldg(&ei[e0 + tid]);
    else if (tid >= EPB && tid < EPB + valid) sc[tid - EPB] = __ldg(&ei[e + e0 + (tid - EPB)]);
    __syncthreads();

    if (valid == EPB) {
#pragma unroll 2
        for (int it = 0; it < 8; it += 2) {
            int le0 = warp * 8 + it, le1 = le0 + 1;
            int r0 = sr[le0], cc0 = sc[le0];
            int r1 = sr[le1], cc1 = sc[le1];
            float2 fa0 = __half22float2(g_hAh[(size_t)r0 * 32 + lane]);
            float2 fb0 = __half22float2(g_hBh[(size_t)cc0 * 32 + lane]);
            float2 fa1 = __half22float2(g_hAh[(size_t)r1 * 32 + lane]);
            float2 fb1 = __half22float2(g_hBh[(size_t)cc1 * 32 + lane]);
            float s00 = fa0.x + fb0.x, s01 = fa0.y + fb0.y;
            float s10 = fa1.x + fb1.x, s11 = fa1.y + fb1.y;
#pragma unroll
            for (int q = 0; q < 4; ++q) {
                float4 a0 = sea[le0 * 4 + q];
                float4 a1 = sea[le1 * 4 + q];
                s00 += a0.x * c0[4 * q] + a0.y * c0[4 * q + 1] + a0.z * c0[4 * q + 2] + a0.w * c0[4 * q + 3];
                s01 += a0.x * c1[4 * q] + a0.y * c1[4 * q + 1] + a0.z * c1[4 * q + 2] + a0.w * c1[4 * q + 3];
                s10 += a1.x * c0[4 * q] + a1.y * c0[4 * q + 1] + a1.z * c0[4 * q + 2] + a1.w * c0[4 * q + 3];
                s11 += a1.x * c1[4 * q] + a1.y * c1[4 * q + 1] + a1.z * c1[4 * q + 2] + a1.w * c1[4 * q + 3];
            }
            float p0 = fmaxf(s00, 0.f) * w2p.x + fmaxf(s01, 0.f) * w2p.y;
            float p1 = fmaxf(s10, 0.f) * w2p.x + fmaxf(s11, 0.f) * w2p.y;
#pragma unroll
            for (int o = 16; o; o >>= 1) {
                p0 += __shfl_xor_sync(0xffffffffu, p0, o);
                p1 += __shfl_xor_sync(0xffffffffu, p1, o);
            }
            if (lane == 0) { sout[le0] = p0 + bb; sout[le1] = p1 + bb; }
        }
    } else {
        for (int it = 0; it < 8; ++it) {
            int le = warp * 8 + it;
            if (le < valid) {
                int r = sr[le], c = sc[le];
                float2 fa = __half22float2(g_hAh[(size_t)r * 32 + lane]);
                float2 fb = __half22float2(g_hBh[(size_t)c * 32 + lane]);
                float s0 = fa.x + fb.x;
                float s1 = fa.y + fb.y;
#pragma unroll
                for (int q = 0; q < 4; ++q) {
                    float4 a = sea[le * 4 + q];
                    s0 += a.x * c0[4 * q] + a.y * c0[4 * q + 1] + a.z * c0[4 * q + 2] + a.w * c0[4 * q + 3];
                    s1 += a.x * c1[4 * q] + a.y * c1[4 * q + 1] + a.z * c1[4 * q + 2] + a.w * c1[4 * q + 3];
                }
                float p = fmaxf(s0, 0.f) * w2p.x + fmaxf(s1, 0.f) * w2p.y;
#pragma unroll
                for (int o = 16; o; o >>= 1) p += __shfl_xor_sync(0xffffffffu, p, o);
                if (lane == 0) sout[le] = p + bb;
            }
        }
    }
    __syncthreads();
    if (tid < valid) out[e0 + tid] = sout[tid];
}

// ---------------- launcher (R7 schedule + xagg under ODE) ----------------
extern "C" void kernel_launch(void* const* d_in, const int* in_sizes, int n_in,
                              void* d_out, int out_size) {
    const float* x_seq = (const float*)d_in[0];
    const float* ea    = (const float*)d_in[1];
    const float* iw    = (const float*)d_in[2];
    const float* W1    = (const float*)d_in[3];
    const float* b1o   = (const float*)d_in[4];
    const float* W2    = (const float*)d_in[5];
    const float* b2o   = (const float*)d_in[6];
    const float* mw1   = (const float*)d_in[7];
    const float* mb1   = (const float*)d_in[8];
    const float* mw2   = (const float*)d_in[9];
    const float* mb2   = (const float*)d_in[10];
    const int*   ei    = (const int*)d_in[11];
    float* out = (float*)d_out;

    const int n = NN;
    const int e = EE;
    const float* xlast = x_seq + (size_t)(T_STEPS - 1) * n * 64;
    const float h = 1.0f / (float)(T_STEPS - 1);

    cudaFuncSetAttribute(ode_persist, cudaFuncAttributeMaxDynamicSharedMemorySize,
                         ODE_SMEM_FLOATS * 4);

    cudaStream_t sB;
    cudaStreamCreateWithFlags(&sB, cudaStreamNonBlocking);
    cudaEvent_t evFork, evInit, evJoin;
    cudaEventCreateWithFlags(&evFork, cudaEventDisableTiming);
    cudaEventCreateWithFlags(&evInit, cudaEventDisableTiming);
    cudaEventCreateWithFlags(&evJoin, cudaEventDisableTiming);

    // main: weight transposes (dependency-free) start immediately
    {
        float* w1t; cudaGetSymbolAddress((void**)&w1t, g_W1t);
        float* w2t; cudaGetSymbolAddress((void**)&w2t, g_W2t);
        dim3 t1g(BN / 32, FLAT / 32);
        transpose_kernel<<<t1g, dim3(32, 8)>>>(W1, w1t, FLAT, BN);
        dim3 t2g(FLAT / 32, BN / 32);
        transpose_kernel<<<t2g, dim3(32, 8)>>>(W2, w2t, BN, FLAT);
    }
    // FORK: sB joins the capture graph via an event from the capturing stream.
    cudaEventRecord(evFork, 0);
    cudaStreamWaitEvent(sB, evFork, 0);

    // stream B: init + CSR chain + W-independent aggregation, all under the ODE
    init_kernel<<<(n + 255) / 256, 256, 0, sB>>>(iw, n);
    cudaEventRecord(evInit, sB);
    count_kernel<<<(e + 255) / 256, 256, 0, sB>>>(ei, e);
    dis_kernel<<<(n + 255) / 256, 256, 0, sB>>>(n);
    zxh_kernel<<<(n * 32 + 255) / 256, 256, 0, sB>>>(xlast, n);
    scan1_kernel<<<NB_SCAN, 1024, 0, sB>>>(n);
    scan2_kernel<<<1, 128, 0, sB>>>(NB_SCAN);
    scan3_kernel<<<NB_SCAN, 1024, 0, sB>>>(n);
    place_kernel<<<(e + 255) / 256, 256, 0, sB>>>(ei, e);
    xagg_kernel<<<(n * 32 + 255) / 256, 256, 0, sB>>>(n);
    cudaEventRecord(evJoin, sB);

    // main: ODE starts as soon as init is done; chain runs under it (R7 schedule).
    cudaStreamWaitEvent(0, evInit, 0);
    ode_persist<<<NB_ODE, 1024, ODE_SMEM_FLOATS * 4>>>(b1o, b2o, h);

    // JOIN: node MLP needs X_agg (sB) + final W (ODE)
    cudaStreamWaitEvent(0, evJoin, 0);
    wxhab_kernel<<<(n + 63) / 64, 256>>>(mw1, mb1, n);
    edge_kernel<<<(e + EPB - 1) / EPB, 256>>>(ea, ei, mw1, mw2, mb2, out, e);

    cudaEventDestroy(evFork);
    cudaEventDestroy(evInit);
    cudaEventDestroy(evJoin);
    cudaStreamDestroy(sB);
}

// round 15
// speedup vs baseline: 1.2518x; 1.0242x over previous
#include <cuda_runtime.h>
#include <cuda_fp16.h>

// Problem constants (fixed by the dataset)
#define T_STEPS 8
#define NN      100000
#define EE      1600000
#define FLAT    4096    // 64*64
#define BN      1024    // bottleneck
#define NB_ODE  128     // persistent ODE grid (1 block/SM, co-resident)
#define NB_SCAN 98      // ceil(NN/1024)
#define EPB     64      // edges per block in edge_kernel

// ---------------- device scratch (no allocs allowed) ----------------
__device__ float  g_w[FLAT];
__device__ float  g_ws[FLAT];
__device__ float  g_t[BN];
__device__ float  g_W1t[BN * FLAT];   // transposed: row j (1024 rows) x k (4096)
__device__ float  g_W2t[FLAT * BN];   // transposed: row j (4096 rows) x k (1024)
__device__ unsigned g_barcnt;
__device__ float  g_dis[NN];
__device__ int    g_cnt[NN];        // in-degree (no self)
__device__ int    g_base[NN + 1];   // CSR row offsets (by destination)
__device__ int    g_cur[NN];        // placement cursors
__device__ int    g_src[EE];        // CSR: source node per in-edge
__device__ int    g_bsum[NB_SCAN];
__device__ int    g_boff[NB_SCAN];
__device__ __align__(16) __half2 g_zh[NN * 32];    // zx = dis[n]*x[n]  fp16 [N,64]
__device__ __align__(16) __half2 g_xaggh[NN * 32]; // aggregated x      fp16 [N,64]
__device__ __align__(16) __half2 g_hAh[NN * 32];   // h@A+b1 fp16       [N,64]
__device__ __align__(16) __half2 g_hBh[NN * 32];   // h@B    fp16       [N,64]

// ---------------- init: copy w0, zero counters, reset barrier ----------------
__global__ void init_kernel(const float* __restrict__ iw, int n) {
    int i = blockIdx.x * 256 + threadIdx.x;
    if (i == 0) g_barcnt = 0u;
    if (i < FLAT) g_w[i] = iw[i];
    if (i < n)    g_cnt[i] = 0;
}

// ---------------- in-degree count ----------------
__global__ void count_kernel(const int* __restrict__ ei, int e) {
    int i = blockIdx.x * 256 + threadIdx.x;
    if (i < e) atomicAdd(&g_cnt[ei[e + i]], 1);
}

// ---------------- dis = rsqrt(deg), deg = cnt + 1 (self loop) ----------------
__global__ void dis_kernel(int n) {
    int i = blockIdx.x * 256 + threadIdx.x;
    if (i < n) g_dis[i] = rsqrtf(1.0f + (float)g_cnt[i]);
}

// ---------------- zx[n] = dis[n] * x_last[n], stored fp16 ----------------
__global__ void zxh_kernel(const float* __restrict__ xlast, int n) {
    int idx = blockIdx.x * 256 + threadIdx.x;     // half2 index
    if (idx < n * 32) {
        int nn = idx >> 5;
        float d = g_dis[nn];
        float2 v = ((const float2*)xlast)[idx];
        g_zh[idx] = __floats2half2_rn(d * v.x, d * v.y);
    }
}

// ---------------- CSR offset scan (3 small kernels) ----------------
__global__ void scan1_kernel(int n) {            // block sums
    __shared__ int sm_[1024];
    int i = blockIdx.x * 1024 + threadIdx.x;
    sm_[threadIdx.x] = (i < n) ? g_cnt[i] : 0;
    __syncthreads();
#pragma unroll
    for (int o = 512; o; o >>= 1) {
        if (threadIdx.x < o) sm_[threadIdx.x] += sm_[threadIdx.x + o];
        __syncthreads();
    }
    if (threadIdx.x == 0) g_bsum[blockIdx.x] = sm_[0];
}

__global__ void scan2_kernel(int nb) {           // serial scan of block sums
    __shared__ int sb[NB_SCAN];
    if (threadIdx.x < nb) sb[threadIdx.x] = g_bsum[threadIdx.x];
    __syncthreads();
    if (threadIdx.x == 0) {
        int run = 0;
        for (int b = 0; b < nb; ++b) { g_boff[b] = run; run += sb[b]; }
        g_base[NN] = run;            // == EE
    }
}

__global__ void scan3_kernel(int n) {            // in-block exclusive scan + offset
    __shared__ int sm_[1024];
    int i = blockIdx.x * 1024 + threadIdx.x;
    int v = (i < n) ? g_cnt[i] : 0;
    sm_[threadIdx.x] = v;
    __syncthreads();
#pragma unroll
    for (int o = 1; o < 1024; o <<= 1) {         // Hillis-Steele inclusive
        int t = (threadIdx.x >= o) ? sm_[threadIdx.x - o] : 0;
        __syncthreads();
        sm_[threadIdx.x] += t;
        __syncthreads();
    }
    if (i < n) {
        int excl = sm_[threadIdx.x] - v + g_boff[blockIdx.x];
        g_base[i] = excl;
        g_cur[i]  = excl;
    }
}

// ---------------- CSR placement ----------------
__global__ void place_kernel(const int* __restrict__ ei, int e) {
    int i = blockIdx.x * 256 + threadIdx.x;
    if (i < e) {
        int c = ei[e + i];
        int p = atomicAdd(&g_cur[c], 1);
        g_src[p] = ei[i];
    }
}

// ---------------- X_agg[c] = dis[c]*(zx[c] + sum_in zx[src]), fp16; W-independent ----------------
__global__ void xagg_kernel(int n) {
    int gw   = (blockIdx.x * 256 + threadIdx.x) >> 5;
    int lane = threadIdx.x & 31;
    if (gw >= n) return;
    int k0 = g_base[gw], k1 = g_base[gw + 1];
    float2 s = __half22float2(g_zh[(size_t)gw * 32 + lane]);   // self-loop term
    for (int kb = k0; kb < k1; kb += 32) {
        int m = k1 - kb; if (m > 32) m = 32;
        int rl = (lane < m) ? __ldg(&g_src[kb + lane]) : 0;
#pragma unroll 4
        for (int j = 0; j < m; ++j) {
            int r = __shfl_sync(0xffffffffu, rl, j);
            float2 v = __half22float2(g_zh[(size_t)r * 32 + lane]);
            s.x += v.x; s.y += v.y;
        }
    }
    float dc = g_dis[gw];
    g_xaggh[(size_t)gw * 32 + lane] = __floats2half2_rn(dc * s.x, dc * s.y);
}

// ---------------- 32x32 tiled transpose: dst[C][R] = src[R][C]^T ----------------
__global__ void transpose_kernel(const float* __restrict__ src, float* __restrict__ dst,
                                 int R, int C) {
    __shared__ float tile[32][33];
    int bx = blockIdx.x * 32, by = blockIdx.y * 32;
    int x = bx + threadIdx.x;
#pragma unroll
    for (int i = 0; i < 32; i += 8) {
        int y = by + threadIdx.y + i;
        tile[threadIdx.y + i][threadIdx.x] = src[(size_t)y * C + x];
    }
    __syncthreads();
    int x2 = by + threadIdx.x;
#pragma unroll
    for (int i = 0; i < 32; i += 8) {
        int y2 = bx + threadIdx.y + i;
        dst[(size_t)y2 * R + x2] = tile[threadIdx.x][threadIdx.y + i];
    }
}

// ---------------- R7 grid barrier: monotonic counter, red.add + acquire poll ----------------
__device__ __forceinline__ void gridsync(unsigned target) {
    __syncthreads();
    if (threadIdx.x == 0) {
        asm volatile("red.add.release.gpu.u32 [%0], %1;"
                     :: "l"(&g_barcnt), "r"(1u) : "memory");
        unsigned v;
        do {
            asm volatile("ld.acquire.gpu.u32 %0, [%1];"
                         : "=r"(v) : "l"(&g_barcnt) : "memory");
        } while (v < target);
    }
    __syncthreads();
}

// ---------------- persistent ODE (R7 byte-for-byte) ----------------
#define ODE_SMEM_FLOATS (32768 + 4096 + 1024 + 32)

__global__ __launch_bounds__(1024, 1)
void ode_persist(const float* __restrict__ b1, const float* __restrict__ b2, float h) {
    extern __shared__ float sm[];
    float* sW1 = sm;
    float* sw  = sm + 32768;
    float* st  = sm + 32768 + 4096;
    float* red = sm + 32768 + 4096 + 1024;   // [8 groups][4 warps]

    const int tid  = threadIdx.x;
    const int b    = blockIdx.x;
    const int lane = tid & 31;
    const int wid  = tid >> 5;
    const int grp  = tid >> 7;
    const int tin  = tid & 127;
    const int wgrp = tin >> 5;

    {
        const float4* src = (const float4*)(g_W1t + ((size_t)b * 8) * 4096);
        float4* dst = (float4*)sW1;
#pragma unroll
        for (int i = 0; i < 8; ++i) dst[tid + 1024 * i] = src[tid + 1024 * i];
    }
    float4 w2r[8];
    {
        const float4* src = (const float4*)(g_W2t + ((size_t)(b * 32 + wid)) * 1024);
#pragma unroll
        for (int i = 0; i < 8; ++i) w2r[i] = src[lane + 32 * i];
    }
    const int   j2  = b * 32 + wid;
    const float b2j = b2[j2];
    float wcur = g_w[j2];
    float k1 = 0.f, k2 = 0.f, k3 = 0.f;
    unsigned tgt = 0;
    __syncthreads();

    for (int stage = 0; stage < 4 * (T_STEPS - 1); ++stage) {
        const int st4 = stage & 3;
        {
            const float4* win = (const float4*)(st4 == 0 ? g_w : g_ws);
            ((float4*)sw)[tid] = __ldcg(win + tid);
        }
        __syncthreads();

        {
            const float4* wrow = (const float4*)(sW1 + (size_t)grp * 4096);
            const float4* sw4  = (const float4*)sw;
            float s = 0.f;
#pragma unroll
            for (int i = 0; i < 8; ++i) {
                float4 a = wrow[tin + 128 * i];
                float4 v = sw4[tin + 128 * i];
                s += a.x * v.x + a.y * v.y + a.z * v.z + a.w * v.w;
            }
#pragma unroll
            for (int o = 16; o; o >>= 1) s += __shfl_xor_sync(0xffffffffu, s, o);
            if (lane == 0) red[grp * 4 + wgrp] = s;
        }
        __syncthreads();
        if (tid < 8) {
            float tot = red[tid * 4] + red[tid * 4 + 1] + red[tid * 4 + 2] + red[tid * 4 + 3];
            g_t[b * 8 + tid] = tanhf(tot + b1[b * 8 + tid]);
        }
        tgt += NB_ODE;
        gridsync(tgt);

        if (tid < 256) ((float4*)st)[tid] = __ldcg(((const float4*)g_t) + tid);
        __syncthreads();
        {
            const float4* st4p = (const float4*)st;
            float s = 0.f;
#pragma unroll
            for (int i = 0; i < 8; ++i) {
                float4 a = w2r[i];
                float4 v = st4p[lane + 32 * i];
                s += a.x * v.x + a.y * v.y + a.z * v.z + a.w * v.w;
            }
#pragma unroll
            for (int o = 16; o; o >>= 1) s += __shfl_xor_sync(0xffffffffu, s, o);
            if (lane == 0) {
                float z = s + b2j;
                if (st4 == 0) {
                    k1 = z;
                    g_ws[j2] = wcur + (h * (1.f / 3.f)) * z;
                } else if (st4 == 1) {
                    k2 = z;
                    g_ws[j2] = wcur + h * (z - k1 * (1.f / 3.f));
                } else if (st4 == 2) {
                    k3 = z;
                    g_ws[j2] = wcur + h * (k1 - k2 + z);
                } else {
                    wcur += h * 0.125f * (k1 + 3.f * (k2 + k3) + z);
                    g_w[j2] = wcur;
                }
            }
        }
        if (stage != 4 * (T_STEPS - 1) - 1) {
            tgt += NB_ODE;
            gridsync(tgt);
        }
    }
}

// ---------------- fused: u = Xagg @ W; h = relu(u); hA = h@A+b1; hB = h@B ----------------
__global__ __launch_bounds__(256)
void wxhab_kernel(const float* __restrict__ mw1, const float* __restrict__ mb1,
                  int n) {
    __shared__ float Ws[64 * 64];
    __shared__ float xs[64 * 64];
    const int tid = threadIdx.x;
    const int n0  = blockIdx.x * 64;

    // stage X_agg tile (fp16 -> fp32)
    for (int i = tid; i < 2048; i += 256) {
        int r = i >> 5, c2 = i & 31, nn = n0 + r;
        float2 v = (nn < n) ? __half22float2(g_xaggh[(size_t)nn * 32 + c2])
                            : make_float2(0.f, 0.f);
        *(float2*)&xs[r * 64 + 2 * c2] = v;
    }
    for (int i = tid; i < 4096; i += 256) Ws[i] = g_w[i];
    __syncthreads();

    int tx = tid & 15, ty = tid >> 4;

    // GEMM 1: u = Xagg @ W
    float acc[4][4] = {};
#pragma unroll 4
    for (int k = 0; k < 64; ++k) {
        float4 b = *(const float4*)&Ws[k * 64 + tx * 4];
#pragma unroll
        for (int i = 0; i < 4; ++i) {
            float a = xs[(ty * 4 + i) * 64 + k];
            acc[i][0] += a * b.x; acc[i][1] += a * b.y;
            acc[i][2] += a * b.z; acc[i][3] += a * b.w;
        }
    }
    __syncthreads();    // all reads of xs done

    // write relu'd u back into xs
#pragma unroll
    for (int i = 0; i < 4; ++i) {
        int row = ty * 4 + i;
        xs[row * 64 + tx * 4 + 0] = fmaxf(acc[i][0], 0.f);
        xs[row * 64 + tx * 4 + 1] = fmaxf(acc[i][1], 0.f);
        xs[row * 64 + tx * 4 + 2] = fmaxf(acc[i][2], 0.f);
        xs[row * 64 + tx * 4 + 3] = fmaxf(acc[i][3], 0.f);
    }

    // GEMM 2/3: hA = h@A + b1 ; hB = h@B
#pragma unroll
    for (int sel = 0; sel < 2; ++sel) {
        __syncthreads();
        for (int i = tid; i < 4096; i += 256) Ws[i] = mw1[sel * 4096 + i];
        __syncthreads();
        float acc2[4][4] = {};
#pragma unroll 4
        for (int k = 0; k < 64; ++k) {
            float4 b = *(const float4*)&Ws[k * 64 + tx * 4];
#pragma unroll
            for (int i = 0; i < 4; ++i) {
                float a = xs[(ty * 4 + i) * 64 + k];
                acc2[i][0] += a * b.x; acc2[i][1] += a * b.y;
                acc2[i][2] += a * b.z; acc2[i][3] += a * b.w;
            }
        }
        float4 bb = make_float4(0.f, 0.f, 0.f, 0.f);
        if (sel == 0) {
            bb.x = mb1[tx * 4 + 0]; bb.y = mb1[tx * 4 + 1];
            bb.z = mb1[tx * 4 + 2]; bb.w = mb1[tx * 4 + 3];
        }
        __half2* out = sel ? g_hBh : g_hAh;
#pragma unroll
        for (int i = 0; i < 4; ++i) {
            int nn = n0 + ty * 4 + i;
            if (nn < n) {
                __half2 h0 = __floats2half2_rn(acc2[i][0] + bb.x, acc2[i][1] + bb.y);
                __half2 h1 = __floats2half2_rn(acc2[i][2] + bb.z, acc2[i][3] + bb.w);
                uint2 pk = make_uint2(*(unsigned*)&h0, *(unsigned*)&h1);
                *(uint2*)&out[(size_t)nn * 32 + tx * 2] = pk;
            }
        }
    }
}

// ---------------- edge MLP: prefetched gathers (MLP 4 -> 16 per warp) ----------------
__global__ __launch_bounds__(256)
void edge_kernel(const float* __restrict__ ea, const int* __restrict__ ei,
                 const float* __restrict__ mw1, const float* __restrict__ w2,
                 const float* __restrict__ b2, float* __restrict__ out, int e) {
    __shared__ float4 sea[EPB * 4];
    __shared__ int   sr[EPB], sc[EPB];
    __shared__ float sout[EPB];
    const int tid  = threadIdx.x;
    const int lane = tid & 31;
    const int warp = tid >> 5;
    const int e0   = blockIdx.x * EPB;
    const int valid = (e - e0 < EPB) ? (e - e0) : EPB;

    float c0[16], c1[16];
#pragma unroll
    for (int f = 0; f < 16; ++f) {
        float2 cc = *(const float2*)&mw1[(128 + f) * 64 + 2 * lane];
        c0[f] = cc.x; c1[f] = cc.y;
    }
    const float2 w2p = *(const float2*)&w2[2 * lane];
    const float  bb  = __ldg(&b2[0]);

    if (tid < valid * 4) sea[tid] = ((const float4*)(ea + (size_t)e0 * 16))[tid];
    if (tid < valid)                sr[tid]       = __ldg(&ei[e0 + tid]);
    else if (tid >= EPB && tid < EPB + valid) sc[tid - EPB] = __ldg(&ei[e + e0 + (tid - EPB)]);
    __syncthreads();

    if (valid == EPB) {
        // prefetch ALL 8 edges' hA/hB rows -> 16 outstanding gathers per warp
        float2 fa[8], fb[8];
#pragma unroll
        for (int i = 0; i < 8; ++i) {
            int le = warp * 8 + i;
            fa[i] = __half22float2(g_hAh[(size_t)sr[le] * 32 + lane]);
            fb[i] = __half22float2(g_hBh[(size_t)sc[le] * 32 + lane]);
        }
#pragma unroll
        for (int it = 0; it < 8; it += 2) {
            int le0 = warp * 8 + it, le1 = le0 + 1;
            float s00 = fa[it].x + fb[it].x,     s01 = fa[it].y + fb[it].y;
            float s10 = fa[it + 1].x + fb[it + 1].x, s11 = fa[it + 1].y + fb[it + 1].y;
#pragma unroll
            for (int q = 0; q < 4; ++q) {
                float4 a0 = sea[le0 * 4 + q];
                float4 a1 = sea[le1 * 4 + q];
                s00 += a0.x * c0[4 * q] + a0.y * c0[4 * q + 1] + a0.z * c0[4 * q + 2] + a0.w * c0[4 * q + 3];
                s01 += a0.x * c1[4 * q] + a0.y * c1[4 * q + 1] + a0.z * c1[4 * q + 2] + a0.w * c1[4 * q + 3];
                s10 += a1.x * c0[4 * q] + a1.y * c0[4 * q + 1] + a1.z * c0[4 * q + 2] + a1.w * c0[4 * q + 3];
                s11 += a1.x * c1[4 * q] + a1.y * c1[4 * q + 1] + a1.z * c1[4 * q + 2] + a1.w * c1[4 * q + 3];
            }
            float p0 = fmaxf(s00, 0.f) * w2p.x + fmaxf(s01, 0.f) * w2p.y;
            float p1 = fmaxf(s10, 0.f) * w2p.x + fmaxf(s11, 0.f) * w2p.y;
#pragma unroll
            for (int o = 16; o; o >>= 1) {
                p0 += __shfl_xor_sync(0xffffffffu, p0, o);
                p1 += __shfl_xor_sync(0xffffffffu, p1, o);
            }
            if (lane == 0) { sout[le0] = p0 + bb; sout[le1] = p1 + bb; }
        }
    } else {
        for (int it = 0; it < 8; ++it) {
            int le = warp * 8 + it;
            if (le < valid) {
                int r = sr[le], c = sc[le];
                float2 fa = __half22float2(g_hAh[(size_t)r * 32 + lane]);
                float2 fb = __half22float2(g_hBh[(size_t)c * 32 + lane]);
                float s0 = fa.x + fb.x;
                float s1 = fa.y + fb.y;
#pragma unroll
                for (int q = 0; q < 4; ++q) {
                    float4 a = sea[le * 4 + q];
                    s0 += a.x * c0[4 * q] + a.y * c0[4 * q + 1] + a.z * c0[4 * q + 2] + a.w * c0[4 * q + 3];
                    s1 += a.x * c1[4 * q] + a.y * c1[4 * q + 1] + a.z * c1[4 * q + 2] + a.w * c1[4 * q + 3];
                }
                float p = fmaxf(s0, 0.f) * w2p.x + fmaxf(s1, 0.f) * w2p.y;
#pragma unroll
                for (int o = 16; o; o >>= 1) p += __shfl_xor_sync(0xffffffffu, p, o);
                if (lane == 0) sout[le] = p + bb;
            }
        }
    }
    __syncthreads();
    if (tid < valid) out[e0 + tid] = sout[tid];
}

// ---------------- launcher (R14 byte-for-byte) ----------------
extern "C" void kernel_launch(void* const* d_in, const int* in_sizes, int n_in,
                              void* d_out, int out_size) {
    const float* x_seq = (const float*)d_in[0];
    const float* ea    = (const float*)d_in[1];
    const float* iw    = (const float*)d_in[2];
    const float* W1    = (const float*)d_in[3];
    const float* b1o   = (const float*)d_in[4];
    const float* W2    = (const float*)d_in[5];
    const float* b2o   = (const float*)d_in[6];
    const float* mw1   = (const float*)d_in[7];
    const float* mb1   = (const float*)d_in[8];
    const float* mw2   = (const float*)d_in[9];
    const float* mb2   = (const float*)d_in[10];
    const int*   ei    = (const int*)d_in[11];
    float* out = (float*)d_out;

    const int n = NN;
    const int e = EE;
    const float* xlast = x_seq + (size_t)(T_STEPS - 1) * n * 64;
    const float h = 1.0f / (float)(T_STEPS - 1);

    cudaFuncSetAttribute(ode_persist, cudaFuncAttributeMaxDynamicSharedMemorySize,
                         ODE_SMEM_FLOATS * 4);

    cudaStream_t sB;
    cudaStreamCreateWithFlags(&sB, cudaStreamNonBlocking);
    cudaEvent_t evFork, evInit, evJoin;
    cudaEventCreateWithFlags(&evFork, cudaEventDisableTiming);
    cudaEventCreateWithFlags(&evInit, cudaEventDisableTiming);
    cudaEventCreateWithFlags(&evJoin, cudaEventDisableTiming);

    // main: weight transposes (dependency-free) start immediately
    {
        float* w1t; cudaGetSymbolAddress((void**)&w1t, g_W1t);
        float* w2t; cudaGetSymbolAddress((void**)&w2t, g_W2t);
        dim3 t1g(BN / 32, FLAT / 32);
        transpose_kernel<<<t1g, dim3(32, 8)>>>(W1, w1t, FLAT, BN);
        dim3 t2g(FLAT / 32, BN / 32);
        transpose_kernel<<<t2g, dim3(32, 8)>>>(W2, w2t, BN, FLAT);
    }
    // FORK: sB joins the capture graph via an event from the capturing stream.
    cudaEventRecord(evFork, 0);
    cudaStreamWaitEvent(sB, evFork, 0);

    // stream B: init + CSR chain + W-independent aggregation, all under the ODE
    init_kernel<<<(n + 255) / 256, 256, 0, sB>>>(iw, n);
    cudaEventRecord(evInit, sB);
    count_kernel<<<(e + 255) / 256, 256, 0, sB>>>(ei, e);
    dis_kernel<<<(n + 255) / 256, 256, 0, sB>>>(n);
    zxh_kernel<<<(n * 32 + 255) / 256, 256, 0, sB>>>(xlast, n);
    scan1_kernel<<<NB_SCAN, 1024, 0, sB>>>(n);
    scan2_kernel<<<1, 128, 0, sB>>>(NB_SCAN);
    scan3_kernel<<<NB_SCAN, 1024, 0, sB>>>(n);
    place_kernel<<<(e + 255) / 256, 256, 0, sB>>>(ei, e);
    xagg_kernel<<<(n * 32 + 255) / 256, 256, 0, sB>>>(n);
    cudaEventRecord(evJoin, sB);

    // main: ODE starts as soon as init is done; chain runs under it (R7 schedule).
    cudaStreamWaitEvent(0, evInit, 0);
    ode_persist<<<NB_ODE, 1024, ODE_SMEM_FLOATS * 4>>>(b1o, b2o, h);

    // JOIN: node MLP needs X_agg (sB) + final W (ODE)
    cudaStreamWaitEvent(0, evJoin, 0);
    wxhab_kernel<<<(n + 63) / 64, 256>>>(mw1, mb1, n);
    edge_kernel<<<(e + EPB - 1) / EPB, 256>>>(ea, ei, mw1, mw2, mb2, out, e);

    cudaEventDestroy(evFork);
    cudaEventDestroy(evInit);
    cudaEventDestroy(evJoin);
    cudaStreamDestroy(sB);
}